// round 11
// baseline (speedup 1.0000x reference)
#include <cuda_runtime.h>
#include <math.h>
#include <stdint.h>

#define BB   16
#define SS   2048
#define DD   768
#define MHID 128
#define NCLS 200
#define NTOK (BB*SS)
#define TM   64
#define NTHR 256
#define OFF_A ((long long)NTOK*DD)
#define OFF_B (OFF_A + (long long)NTOK*10)

#define M_TOT  247357937827LL
#define M_HALF 123678968913LL

// ---- SMEM layout (main kernel) ----
#define SM_A0   0
#define SM_A1   9216
#define SM_B0   18432
#define SM_B1   35840
#define SM_B2   0
#define SM_LOG  0
#define SM_HID  69632          // 64*132*4 = 33792
#define SM_DIG  103424         // 64*20*4  = 5120
#define SM_RES  108544         // 64*9*4   = 2304
#define SM_TOTAL 110848

#define A_STR 36
#define B_STR 136
#define H_STR 132
#define L_STR 104

static __device__ int   g_op[BB];
static __device__ float g_eq[BB];
static __device__ float g_msb[(long long)NTOK * 12];   // msb digits + sign

__device__ const int d_P[9] = {7,11,13,17,19,23,29,31,37};
__device__ const float d_P10F[9][10] = {
  {1,3,2,6,4,5,1,3,2,6},
  {1,10,1,10,1,10,1,10,1,10},
  {1,10,9,12,3,4,1,10,9,12},
  {1,10,15,14,4,6,9,5,16,7},
  {1,10,5,12,6,3,11,15,17,18},
  {1,10,8,11,18,19,6,14,2,20},
  {1,10,13,14,24,8,22,17,25,18},
  {1,10,7,8,18,25,2,20,14,16},
  {1,10,26,1,10,26,1,10,26,1}};
__device__ const long long d_CRT[9] = {
  35336848261LL, 224870852570LL, 114165202074LL, 218257003965LL,
  78113032998LL, 53773464745LL, 68236672504LL, 223420072876LL,
  220616539143LL};

__device__ __forceinline__ float tf32r(float x) {
  uint32_t u;
  asm("cvt.rna.tf32.f32 %0, %1;" : "=r"(u) : "f"(x));
  return __uint_as_float(u);
}

__device__ __forceinline__ void mma_tf32(float* c, const uint32_t* a,
                                         const uint32_t* b) {
  asm volatile(
    "mma.sync.aligned.m16n8k8.row.col.f32.tf32.tf32.f32 "
    "{%0,%1,%2,%3}, {%4,%5,%6,%7}, {%8,%9}, {%0,%1,%2,%3};"
    : "+f"(c[0]), "+f"(c[1]), "+f"(c[2]), "+f"(c[3])
    : "r"(a[0]), "r"(a[1]), "r"(a[2]), "r"(a[3]), "r"(b[0]), "r"(b[1]));
}

__device__ __forceinline__ long long modpow6(long long base, long long e, long long p) {
  long long res = 1, b = base % p;
  #pragma unroll
  for (int i = 0; i < 6; i++) {
    if (e & 1) res = res * b % p;
    b = b * b % p;
    e >>= 1;
  }
  return res;
}

// ---------------------------------------------------------------------------
__global__ void prep_kernel(const int* __restrict__ ids) {
  int w = threadIdx.x >> 5, lane = threadIdx.x & 31;
  if (w >= BB) return;
  const int* row = ids + w * SS;
  int minpos = SS, eq = 0;
  for (int i = lane; i < SS; i += 32) {
    int t = row[i];
    eq |= (t == 28);
    if (t >= 20 && t <= 24) minpos = min(minpos, i);
  }
  #pragma unroll
  for (int off = 16; off; off >>= 1) {
    minpos = min(minpos, __shfl_xor_sync(0xffffffffu, minpos, off));
    eq    |= __shfl_xor_sync(0xffffffffu, eq, off);
  }
  if (lane == 0) {
    int pos = (minpos < SS) ? minpos : 0;
    int t = row[pos];
    g_op[w] = (t >= 20 && t <= 24) ? (t - 20) : -1;
    g_eq[w] = eq ? 1.0f : 0.0f;
  }
}

// ---------------------------------------------------------------------------
// Main kernel: GEMM1 + GEMM2 + softmax + decode + CRT + msb (to g_msb)
// ---------------------------------------------------------------------------
__global__ void __launch_bounds__(NTHR, 2)
main_kernel(const float* __restrict__ h,  const float* __restrict__ W1,
            const float* __restrict__ b1, const float* __restrict__ W2,
            const float* __restrict__ b2, float* __restrict__ out) {
  extern __shared__ char sm[];
  const int tid  = threadIdx.x;
  const int wid  = tid >> 5;
  const int lane = tid & 31;
  const int tok0 = blockIdx.x * TM;
  const int batch = tok0 / SS;

  float* sHid = (float*)(sm + SM_HID);
  float* sLog = (float*)(sm + SM_LOG);
  float* sDig = (float*)(sm + SM_DIG);
  int*   sRes = (int*)(sm + SM_RES);
  float* Ab[2] = {(float*)(sm + SM_A0), (float*)(sm + SM_A1)};
  float* Bb[2] = {(float*)(sm + SM_B0), (float*)(sm + SM_B1)};
  float* B2 = (float*)(sm + SM_B2);

  // warp tiling: 2x4 warps, each 32 rows x 32 cols
  const int g = lane >> 2, t = lane & 3;
  const int warp_row = (wid & 1) * 32;
  const int warp_col = (wid >> 1) * 32;

  // ============ GEMM1 (tf32 mma.sync): hid = relu(h @ W1 + b1) =============
  float acc[2][4][4];
  #pragma unroll
  for (int mt = 0; mt < 2; mt++)
    #pragma unroll
    for (int nt = 0; nt < 4; nt++)
      #pragma unroll
      for (int i = 0; i < 4; i++) acc[mt][nt][i] = 0.0f;

  #pragma unroll
  for (int r = 0; r < 2; r++) {
    int idx = tid + r * 256;
    int ar = idx >> 3, ac4 = idx & 7;
    float4 v = *(const float4*)(h + (long long)(tok0 + ar) * DD + ac4 * 4);
    v.x = tf32r(v.x); v.y = tf32r(v.y); v.z = tf32r(v.z); v.w = tf32r(v.w);
    *(float4*)(Ab[0] + ar * A_STR + ac4 * 4) = v;
  }
  #pragma unroll
  for (int r = 0; r < 4; r++) {
    int idx = tid + r * 256;
    int br = idx >> 5, bc4 = idx & 31;
    float4 w = *(const float4*)(W1 + br * MHID + bc4 * 4);
    w.x = tf32r(w.x); w.y = tf32r(w.y); w.z = tf32r(w.z); w.w = tf32r(w.w);
    *(float4*)(Bb[0] + br * B_STR + bc4 * 4) = w;
  }
  __syncthreads();

  for (int c = 0; c < 24; c++) {
    int cur = c & 1;
    float4 pa[2], pb[4];
    if (c < 23) {
      int k0n = (c + 1) * 32;
      #pragma unroll
      for (int r = 0; r < 2; r++) {
        int idx = tid + r * 256;
        int ar = idx >> 3, ac4 = idx & 7;
        pa[r] = *(const float4*)(h + (long long)(tok0 + ar) * DD + k0n + ac4 * 4);
      }
      #pragma unroll
      for (int r = 0; r < 4; r++) {
        int idx = tid + r * 256;
        int br = idx >> 5, bc4 = idx & 31;
        pb[r] = *(const float4*)(W1 + (k0n + br) * MHID + bc4 * 4);
      }
    }
    const float* A = Ab[cur];
    const float* B = Bb[cur];
    #pragma unroll
    for (int ks = 0; ks < 4; ks++) {
      uint32_t af[2][4];
      #pragma unroll
      for (int mt = 0; mt < 2; mt++) {
        const float* ap = A + (warp_row + mt * 16 + g) * A_STR + ks * 8 + t;
        af[mt][0] = __float_as_uint(ap[0]);
        af[mt][1] = __float_as_uint(ap[8 * A_STR]);
        af[mt][2] = __float_as_uint(ap[4]);
        af[mt][3] = __float_as_uint(ap[8 * A_STR + 4]);
      }
      uint32_t bf[4][2];
      #pragma unroll
      for (int nt = 0; nt < 4; nt++) {
        const float* bp = B + (ks * 8 + t) * B_STR + warp_col + nt * 8 + g;
        bf[nt][0] = __float_as_uint(bp[0]);
        bf[nt][1] = __float_as_uint(bp[4 * B_STR]);
      }
      #pragma unroll
      for (int mt = 0; mt < 2; mt++)
        #pragma unroll
        for (int nt = 0; nt < 4; nt++)
          mma_tf32(acc[mt][nt], af[mt], bf[nt]);
    }
    __syncthreads();
    if (c < 23) {
      int nxt = (c + 1) & 1;
      #pragma unroll
      for (int r = 0; r < 2; r++) {
        int idx = tid + r * 256;
        int ar = idx >> 3, ac4 = idx & 7;
        float4 v = pa[r];
        v.x = tf32r(v.x); v.y = tf32r(v.y); v.z = tf32r(v.z); v.w = tf32r(v.w);
        *(float4*)(Ab[nxt] + ar * A_STR + ac4 * 4) = v;
      }
      #pragma unroll
      for (int r = 0; r < 4; r++) {
        int idx = tid + r * 256;
        int br = idx >> 5, bc4 = idx & 31;
        float4 w = pb[r];
        w.x = tf32r(w.x); w.y = tf32r(w.y); w.z = tf32r(w.z); w.w = tf32r(w.w);
        *(float4*)(Bb[nxt] + br * B_STR + bc4 * 4) = w;
      }
      __syncthreads();
    }
  }
  __syncthreads();

  // ---- GEMM1 epilogue: bias + relu + tf32 -> sHid ----
  #pragma unroll
  for (int mt = 0; mt < 2; mt++) {
    int row0 = warp_row + mt * 16 + g;
    #pragma unroll
    for (int nt = 0; nt < 4; nt++) {
      int col = warp_col + nt * 8 + 2 * t;
      float bx = b1[col], by = b1[col + 1];
      sHid[row0 * H_STR + col]       = tf32r(fmaxf(acc[mt][nt][0] + bx, 0.0f));
      sHid[row0 * H_STR + col + 1]   = tf32r(fmaxf(acc[mt][nt][1] + by, 0.0f));
      sHid[(row0+8) * H_STR + col]   = tf32r(fmaxf(acc[mt][nt][2] + bx, 0.0f));
      sHid[(row0+8) * H_STR + col+1] = tf32r(fmaxf(acc[mt][nt][3] + by, 0.0f));
    }
  }
  __syncthreads();

  // ============ GEMM2 (tf32 mma.sync) in 2 passes of 100 cols ==============
  for (int p = 0; p < 2; p++) {
    #pragma unroll
    for (int r = 0; r < 16; r++) {
      int idx = tid + r * 256;
      int br = idx >> 5, bc4 = idx & 31;
      float4 w;
      if (bc4 < 25) {
        w = *(const float4*)(W2 + br * NCLS + p * 100 + bc4 * 4);
        w.x = tf32r(w.x); w.y = tf32r(w.y); w.z = tf32r(w.z); w.w = tf32r(w.w);
      } else {
        w.x = w.y = w.z = w.w = 0.0f;
      }
      *(float4*)(B2 + br * B_STR + bc4 * 4) = w;
    }
    __syncthreads();

    #pragma unroll
    for (int mt = 0; mt < 2; mt++)
      #pragma unroll
      for (int nt = 0; nt < 4; nt++)
        #pragma unroll
        for (int i = 0; i < 4; i++) acc[mt][nt][i] = 0.0f;

    #pragma unroll 4
    for (int ks = 0; ks < 16; ks++) {
      uint32_t af[2][4];
      #pragma unroll
      for (int mt = 0; mt < 2; mt++) {
        const float* ap = sHid + (warp_row + mt * 16 + g) * H_STR + ks * 8 + t;
        af[mt][0] = __float_as_uint(ap[0]);
        af[mt][1] = __float_as_uint(ap[8 * H_STR]);
        af[mt][2] = __float_as_uint(ap[4]);
        af[mt][3] = __float_as_uint(ap[8 * H_STR + 4]);
      }
      uint32_t bf[4][2];
      #pragma unroll
      for (int nt = 0; nt < 4; nt++) {
        const float* bp = B2 + (ks * 8 + t) * B_STR + warp_col + nt * 8 + g;
        bf[nt][0] = __float_as_uint(bp[0]);
        bf[nt][1] = __float_as_uint(bp[4 * B_STR]);
      }
      #pragma unroll
      for (int mt = 0; mt < 2; mt++)
        #pragma unroll
        for (int nt = 0; nt < 4; nt++)
          mma_tf32(acc[mt][nt], af[mt], bf[nt]);
    }
    __syncthreads();   // all warps done reading B2 before sLog overwrites it

    #pragma unroll
    for (int mt = 0; mt < 2; mt++) {
      int row0 = warp_row + mt * 16 + g;
      #pragma unroll
      for (int nt = 0; nt < 4; nt++) {
        int col = warp_col + nt * 8 + 2 * t;
        if (col < 100) {
          sLog[row0 * L_STR + col]       = acc[mt][nt][0];
          sLog[row0 * L_STR + col + 1]   = acc[mt][nt][1];
          sLog[(row0+8) * L_STR + col]   = acc[mt][nt][2];
          sLog[(row0+8) * L_STR + col+1] = acc[mt][nt][3];
        }
      }
    }
    __syncthreads();

    for (int ti = tid; ti < TM * 10; ti += NTHR) {
      int tok = ti / 10, cgl = ti % 10;
      int cg = p * 10 + cgl;
      float l[10];
      #pragma unroll
      for (int cc = 0; cc < 10; cc++)
        l[cc] = sLog[tok * L_STR + cgl * 10 + cc] + b2[cg * 10 + cc];
      float mx = l[0];
      #pragma unroll
      for (int cc = 1; cc < 10; cc++) mx = fmaxf(mx, l[cc]);
      float sum = 0.0f, num = 0.0f;
      #pragma unroll
      for (int cc = 0; cc < 10; cc++) {
        float e = expf(l[cc] - mx);
        sum += e; num += (float)cc * e;
      }
      float dig = num / sum;
      sDig[tok * 20 + cg] = dig;
      long long gtok = tok0 + tok;
      if (cg < 10) out[OFF_A + gtok * 10 + cg]        = dig;
      else         out[OFF_B + gtok * 10 + (cg - 10)] = dig;
    }
    __syncthreads();
  }

  // ============= modular decode of selected op, per (token, prime) =========
  const int op = g_op[batch];
  if (op >= 0) {
    for (int task = tid; task < TM * 9; task += NTHR) {
      int tok = task / 9, pr = task % 9;
      const float* dg = &sDig[tok * 20];
      float ua = 0.0f, ub = 0.0f;
      #pragma unroll
      for (int k = 0; k < 10; k++) {
        float pw = d_P10F[pr][k];
        ua = fmaf(dg[k],      pw, ua);
        ub = fmaf(dg[10 + k], pw, ub);
      }
      long long pp = d_P[pr];
      float pf = (float)pp;
      long long r;
      if (op == 0) {
        r = llrintf(fmodf(ua + ub, pf)) % pp;
      } else if (op == 1) {
        long long tt = llrintf(fmodf(ua - ub, pf)) % pp;
        r = (tt + pp) % pp;
      } else {
        long long ra = llrintf(fmodf(ua, pf)) % pp;
        long long rb = llrintf(fmodf(ub, pf)) % pp;
        if (op == 2)      r = ra * rb % pp;
        else if (op == 3) r = modpow6(ra, rb, pp);
        else {
          long long inv = modpow6(rb, pp - 2, pp);
          r = (rb == 0) ? 0 : (ra * inv % pp);
        }
      }
      sRes[tok * 9 + pr] = (int)r;
    }
  }
  __syncthreads();

  // ===================== CRT + digits + msb reorder -> g_msb ===============
  if (tid < TM) {
    long long d[10];
    float sign = 0.0f;
    if (op >= 0) {
      long long n = 0;
      #pragma unroll
      for (int pr = 0; pr < 9; pr++)
        n += (long long)sRes[tid * 9 + pr] * d_CRT[pr];
      n %= M_TOT;
      if (op == 1 && n > M_HALF) n -= M_TOT;
      long long a = (n < 0) ? -n : n;
      if (op == 1) sign = (n < 0) ? 1.0f : 0.0f;
      long long tt = a;
      #pragma unroll
      for (int k = 0; k < 10; k++) { d[k] = tt % 10; tt /= 10; }
    } else {
      #pragma unroll
      for (int k = 0; k < 10; k++) d[k] = 0;
    }
    int hi = -1;
    #pragma unroll
    for (int k = 0; k < 10; k++) if (d[k] != 0) hi = k;
    int ns = (hi >= 0) ? hi + 1 : 1;
    float* gm = g_msb + (long long)(tok0 + tid) * 12;
    #pragma unroll
    for (int i = 0; i < 10; i++)
      gm[i] = (i < ns) ? (float)d[ns - 1 - i] : -1.0f;
    gm[10] = sign;
    gm[11] = 0.0f;
  }
}

// ---------------------------------------------------------------------------
// Inject kernel: out = h + gate*eq*(msb @ Winj + binj). 32 tokens/CTA.
// ---------------------------------------------------------------------------
__global__ void inject_kernel(const float* __restrict__ h,
                              const float* __restrict__ Winj,
                              const float* __restrict__ binj,
                              const float* __restrict__ gatep,
                              float* __restrict__ out) {
  __shared__ float smb[32 * 12];
  const int tok0 = blockIdx.x * 32;
  const int batch = tok0 / SS;
  const int c = threadIdx.x;          // 0..191, f4 column

  for (int i = c; i < 32 * 12; i += 192)
    smb[i] = g_msb[(long long)tok0 * 12 + i];
  __syncthreads();

  float4 wv[11];
  #pragma unroll
  for (int k = 0; k < 11; k++)
    wv[k] = *(const float4*)(Winj + k * DD + c * 4);
  float4 bj = *(const float4*)(binj + c * 4);
  float gate = (1.0f / (1.0f + expf(-gatep[0]))) * g_eq[batch];

  #pragma unroll 4
  for (int t = 0; t < 32; t++) {
    long long base = (long long)(tok0 + t) * DD + c * 4;
    float4 hv = *(const float4*)(h + base);
    float4 inj = bj;
    #pragma unroll
    for (int k = 0; k < 11; k++) {
      float m = smb[t * 12 + k];
      inj.x = fmaf(m, wv[k].x, inj.x);
      inj.y = fmaf(m, wv[k].y, inj.y);
      inj.z = fmaf(m, wv[k].z, inj.z);
      inj.w = fmaf(m, wv[k].w, inj.w);
    }
    float4 o;
    o.x = hv.x + gate * inj.x;
    o.y = hv.y + gate * inj.y;
    o.z = hv.z + gate * inj.z;
    o.w = hv.w + gate * inj.w;
    *(float4*)(out + base) = o;
  }
}

// ---------------------------------------------------------------------------
extern "C" void kernel_launch(void* const* d_in, const int* in_sizes, int n_in,
                              void* d_out, int out_size) {
  (void)in_sizes; (void)n_in; (void)out_size;
  const float* h    = (const float*)d_in[0];
  const float* W1   = (const float*)d_in[1];
  const float* b1   = (const float*)d_in[2];
  const float* W2   = (const float*)d_in[3];
  const float* b2   = (const float*)d_in[4];
  const float* Winj = (const float*)d_in[5];
  const float* binj = (const float*)d_in[6];
  const float* gate = (const float*)d_in[7];
  const int*   ids  = (const int*)d_in[8];
  float* out = (float*)d_out;

  prep_kernel<<<1, 512>>>(ids);

  cudaFuncSetAttribute(main_kernel, cudaFuncAttributeMaxDynamicSharedMemorySize,
                       SM_TOTAL);
  main_kernel<<<NTOK / TM, NTHR, SM_TOTAL>>>(h, W1, b1, W2, b2, out);

  inject_kernel<<<NTOK / 32, 192>>>(h, Winj, binj, gate, out);
}

// round 12
// speedup vs baseline: 1.0250x; 1.0250x over previous
#include <cuda_runtime.h>
#include <math.h>
#include <stdint.h>

#define BB   16
#define SS   2048
#define DD   768
#define MHID 128
#define NCLS 200
#define NTOK (BB*SS)
#define TM   64
#define NTHR 256
#define OFF_A ((long long)NTOK*DD)
#define OFF_B (OFF_A + (long long)NTOK*10)

#define M_TOT  247357937827LL
#define M_HALF 123678968913LL

// ---- SMEM layout ----
#define SM_A0   0
#define SM_A1   9216
#define SM_B0   18432
#define SM_B1   35840
#define SM_B2   0
#define SM_LOG  0
#define SM_HID  69632          // 64*132*4 = 33792
#define SM_DIG  103424         // 64*20*4  = 5120
#define SM_RES  108544         // 64*9*4   = 2304
#define SM_MSB  110848         // 64*12*4  = 3072
#define SM_TOTAL 113920

#define A_STR 36
#define B_STR 136
#define H_STR 132
#define L_STR 104

static __device__ int   g_op[BB];
static __device__ float g_eq[BB];

__device__ const int d_P[9] = {7,11,13,17,19,23,29,31,37};
__device__ const float d_P10F[9][10] = {
  {1,3,2,6,4,5,1,3,2,6},
  {1,10,1,10,1,10,1,10,1,10},
  {1,10,9,12,3,4,1,10,9,12},
  {1,10,15,14,4,6,9,5,16,7},
  {1,10,5,12,6,3,11,15,17,18},
  {1,10,8,11,18,19,6,14,2,20},
  {1,10,13,14,24,8,22,17,25,18},
  {1,10,7,8,18,25,2,20,14,16},
  {1,10,26,1,10,26,1,10,26,1}};
__device__ const long long d_CRT[9] = {
  35336848261LL, 224870852570LL, 114165202074LL, 218257003965LL,
  78113032998LL, 53773464745LL, 68236672504LL, 223420072876LL,
  220616539143LL};

__device__ __forceinline__ float tf32r(float x) {
  uint32_t u;
  asm("cvt.rna.tf32.f32 %0, %1;" : "=r"(u) : "f"(x));
  return __uint_as_float(u);
}

__device__ __forceinline__ void mma_tf32(float* c, const uint32_t* a,
                                         const uint32_t* b) {
  asm volatile(
    "mma.sync.aligned.m16n8k8.row.col.f32.tf32.tf32.f32 "
    "{%0,%1,%2,%3}, {%4,%5,%6,%7}, {%8,%9}, {%0,%1,%2,%3};"
    : "+f"(c[0]), "+f"(c[1]), "+f"(c[2]), "+f"(c[3])
    : "r"(a[0]), "r"(a[1]), "r"(a[2]), "r"(a[3]), "r"(b[0]), "r"(b[1]));
}

__device__ __forceinline__ long long modpow6(long long base, long long e, long long p) {
  long long res = 1, b = base % p;
  #pragma unroll
  for (int i = 0; i < 6; i++) {
    if (e & 1) res = res * b % p;
    b = b * b % p;
    e >>= 1;
  }
  return res;
}

// ---------------------------------------------------------------------------
// Prep: one CTA per batch row.
// ---------------------------------------------------------------------------
__global__ void prep_kernel(const int* __restrict__ ids) {
  __shared__ int s_min[8], s_eq[8];
  const int b = blockIdx.x;
  const int* row = ids + b * SS;
  int tid = threadIdx.x, lane = tid & 31, w = tid >> 5;
  int minpos = SS, eq = 0;
  for (int i = tid; i < SS; i += 256) {
    int t = row[i];
    eq |= (t == 28);
    if (t >= 20 && t <= 24) minpos = min(minpos, i);
  }
  #pragma unroll
  for (int off = 16; off; off >>= 1) {
    minpos = min(minpos, __shfl_xor_sync(0xffffffffu, minpos, off));
    eq    |= __shfl_xor_sync(0xffffffffu, eq, off);
  }
  if (lane == 0) { s_min[w] = minpos; s_eq[w] = eq; }
  __syncthreads();
  if (tid == 0) {
    int mp = SS, e = 0;
    #pragma unroll
    for (int i = 0; i < 8; i++) { mp = min(mp, s_min[i]); e |= s_eq[i]; }
    int pos = (mp < SS) ? mp : 0;
    int t = row[pos];
    g_op[b] = (t >= 20 && t <= 24) ? (t - 20) : -1;
    g_eq[b] = e ? 1.0f : 0.0f;
  }
}

// ---------------------------------------------------------------------------
// Main fused kernel
// ---------------------------------------------------------------------------
__global__ void __launch_bounds__(NTHR, 2)
main_kernel(const float* __restrict__ h,  const float* __restrict__ W1,
            const float* __restrict__ b1, const float* __restrict__ W2,
            const float* __restrict__ b2, const float* __restrict__ Winj,
            const float* __restrict__ binj, const float* __restrict__ gatep,
            float* __restrict__ out) {
  extern __shared__ char sm[];
  const int tid  = threadIdx.x;
  const int wid  = tid >> 5;
  const int lane = tid & 31;
  const int tok0 = blockIdx.x * TM;
  const int batch = tok0 / SS;

  float* sHid = (float*)(sm + SM_HID);
  float* sLog = (float*)(sm + SM_LOG);
  float* sDig = (float*)(sm + SM_DIG);
  int*   sRes = (int*)(sm + SM_RES);
  float* sMsb = (float*)(sm + SM_MSB);
  float* Ab[2] = {(float*)(sm + SM_A0), (float*)(sm + SM_A1)};
  float* Bb[2] = {(float*)(sm + SM_B0), (float*)(sm + SM_B1)};
  float* B2 = (float*)(sm + SM_B2);

  // warp tiling: 2x4 warps, each 32 rows x 32 cols
  const int g = lane >> 2, t = lane & 3;
  const int warp_row = (wid & 1) * 32;
  const int warp_col = (wid >> 1) * 32;

  // ============ GEMM1 (tf32 mma.sync): hid = relu(h @ W1 + b1) =============
  float acc[2][4][4];
  #pragma unroll
  for (int mt = 0; mt < 2; mt++)
    #pragma unroll
    for (int nt = 0; nt < 4; nt++)
      #pragma unroll
      for (int i = 0; i < 4; i++) acc[mt][nt][i] = 0.0f;

  #pragma unroll
  for (int r = 0; r < 2; r++) {
    int idx = tid + r * 256;
    int ar = idx >> 3, ac4 = idx & 7;
    float4 v = *(const float4*)(h + (long long)(tok0 + ar) * DD + ac4 * 4);
    v.x = tf32r(v.x); v.y = tf32r(v.y); v.z = tf32r(v.z); v.w = tf32r(v.w);
    *(float4*)(Ab[0] + ar * A_STR + ac4 * 4) = v;
  }
  #pragma unroll
  for (int r = 0; r < 4; r++) {
    int idx = tid + r * 256;
    int br = idx >> 5, bc4 = idx & 31;
    float4 w = *(const float4*)(W1 + br * MHID + bc4 * 4);
    w.x = tf32r(w.x); w.y = tf32r(w.y); w.z = tf32r(w.z); w.w = tf32r(w.w);
    *(float4*)(Bb[0] + br * B_STR + bc4 * 4) = w;
  }
  __syncthreads();

  for (int c = 0; c < 24; c++) {
    int cur = c & 1;
    float4 pa[2], pb[4];
    if (c < 23) {
      int k0n = (c + 1) * 32;
      #pragma unroll
      for (int r = 0; r < 2; r++) {
        int idx = tid + r * 256;
        int ar = idx >> 3, ac4 = idx & 7;
        pa[r] = *(const float4*)(h + (long long)(tok0 + ar) * DD + k0n + ac4 * 4);
      }
      #pragma unroll
      for (int r = 0; r < 4; r++) {
        int idx = tid + r * 256;
        int br = idx >> 5, bc4 = idx & 31;
        pb[r] = *(const float4*)(W1 + (k0n + br) * MHID + bc4 * 4);
      }
    }
    const float* A = Ab[cur];
    const float* B = Bb[cur];
    #pragma unroll
    for (int ks = 0; ks < 4; ks++) {
      uint32_t af[2][4];
      #pragma unroll
      for (int mt = 0; mt < 2; mt++) {
        const float* ap = A + (warp_row + mt * 16 + g) * A_STR + ks * 8 + t;
        af[mt][0] = __float_as_uint(ap[0]);
        af[mt][1] = __float_as_uint(ap[8 * A_STR]);
        af[mt][2] = __float_as_uint(ap[4]);
        af[mt][3] = __float_as_uint(ap[8 * A_STR + 4]);
      }
      uint32_t bf[4][2];
      #pragma unroll
      for (int nt = 0; nt < 4; nt++) {
        const float* bp = B + (ks * 8 + t) * B_STR + warp_col + nt * 8 + g;
        bf[nt][0] = __float_as_uint(bp[0]);
        bf[nt][1] = __float_as_uint(bp[4 * B_STR]);
      }
      #pragma unroll
      for (int mt = 0; mt < 2; mt++)
        #pragma unroll
        for (int nt = 0; nt < 4; nt++)
          mma_tf32(acc[mt][nt], af[mt], bf[nt]);
    }
    __syncthreads();
    if (c < 23) {
      int nxt = (c + 1) & 1;
      #pragma unroll
      for (int r = 0; r < 2; r++) {
        int idx = tid + r * 256;
        int ar = idx >> 3, ac4 = idx & 7;
        float4 v = pa[r];
        v.x = tf32r(v.x); v.y = tf32r(v.y); v.z = tf32r(v.z); v.w = tf32r(v.w);
        *(float4*)(Ab[nxt] + ar * A_STR + ac4 * 4) = v;
      }
      #pragma unroll
      for (int r = 0; r < 4; r++) {
        int idx = tid + r * 256;
        int br = idx >> 5, bc4 = idx & 31;
        float4 w = pb[r];
        w.x = tf32r(w.x); w.y = tf32r(w.y); w.z = tf32r(w.z); w.w = tf32r(w.w);
        *(float4*)(Bb[nxt] + br * B_STR + bc4 * 4) = w;
      }
      __syncthreads();
    }
  }
  __syncthreads();

  // ---- GEMM1 epilogue: bias + relu + tf32 -> sHid ----
  #pragma unroll
  for (int mt = 0; mt < 2; mt++) {
    int row0 = warp_row + mt * 16 + g;
    #pragma unroll
    for (int nt = 0; nt < 4; nt++) {
      int col = warp_col + nt * 8 + 2 * t;
      float bx = b1[col], by = b1[col + 1];
      sHid[row0 * H_STR + col]       = tf32r(fmaxf(acc[mt][nt][0] + bx, 0.0f));
      sHid[row0 * H_STR + col + 1]   = tf32r(fmaxf(acc[mt][nt][1] + by, 0.0f));
      sHid[(row0+8) * H_STR + col]   = tf32r(fmaxf(acc[mt][nt][2] + bx, 0.0f));
      sHid[(row0+8) * H_STR + col+1] = tf32r(fmaxf(acc[mt][nt][3] + by, 0.0f));
    }
  }
  __syncthreads();

  // ============ GEMM2 (tf32 mma.sync) in 2 passes of 100 cols ==============
  // zero-fill the pad region of B2 once (cols 100..127 of every k row)
  for (int idx = tid; idx < 128 * 7; idx += 256) {   // 7 f4 per row
    int br = idx / 7, bc4 = 25 + idx % 7;
    float4 z; z.x = z.y = z.z = z.w = 0.0f;
    *(float4*)(B2 + br * B_STR + bc4 * 4) = z;
  }
  for (int p = 0; p < 2; p++) {
    #pragma unroll
    for (int r = 0; r < 13; r++) {
      int idx = tid + r * 256;            // 3200 f4 real loads
      if (idx < 3200) {
        int br = idx / 25, bc4 = idx % 25;
        float4 w = *(const float4*)(W2 + br * NCLS + p * 100 + bc4 * 4);
        w.x = tf32r(w.x); w.y = tf32r(w.y); w.z = tf32r(w.z); w.w = tf32r(w.w);
        *(float4*)(B2 + br * B_STR + bc4 * 4) = w;
      }
    }
    __syncthreads();

    #pragma unroll
    for (int mt = 0; mt < 2; mt++)
      #pragma unroll
      for (int nt = 0; nt < 4; nt++)
        #pragma unroll
        for (int i = 0; i < 4; i++) acc[mt][nt][i] = 0.0f;

    #pragma unroll 4
    for (int ks = 0; ks < 16; ks++) {
      uint32_t af[2][4];
      #pragma unroll
      for (int mt = 0; mt < 2; mt++) {
        const float* ap = sHid + (warp_row + mt * 16 + g) * H_STR + ks * 8 + t;
        af[mt][0] = __float_as_uint(ap[0]);
        af[mt][1] = __float_as_uint(ap[8 * H_STR]);
        af[mt][2] = __float_as_uint(ap[4]);
        af[mt][3] = __float_as_uint(ap[8 * H_STR + 4]);
      }
      uint32_t bf[4][2];
      #pragma unroll
      for (int nt = 0; nt < 4; nt++) {
        const float* bp = B2 + (ks * 8 + t) * B_STR + warp_col + nt * 8 + g;
        bf[nt][0] = __float_as_uint(bp[0]);
        bf[nt][1] = __float_as_uint(bp[4 * B_STR]);
      }
      #pragma unroll
      for (int mt = 0; mt < 2; mt++)
        #pragma unroll
        for (int nt = 0; nt < 4; nt++)
          mma_tf32(acc[mt][nt], af[mt], bf[nt]);
    }
    __syncthreads();   // all warps done reading B2 before sLog overwrites it

    #pragma unroll
    for (int mt = 0; mt < 2; mt++) {
      int row0 = warp_row + mt * 16 + g;
      #pragma unroll
      for (int nt = 0; nt < 4; nt++) {
        int col = warp_col + nt * 8 + 2 * t;
        if (col < 100) {
          sLog[row0 * L_STR + col]       = acc[mt][nt][0];
          sLog[row0 * L_STR + col + 1]   = acc[mt][nt][1];
          sLog[(row0+8) * L_STR + col]   = acc[mt][nt][2];
          sLog[(row0+8) * L_STR + col+1] = acc[mt][nt][3];
        }
      }
    }
    __syncthreads();

    for (int ti = tid; ti < TM * 10; ti += NTHR) {
      int tok = ti / 10, cgl = ti % 10;
      int cg = p * 10 + cgl;
      float l[10];
      #pragma unroll
      for (int cc = 0; cc < 10; cc++)
        l[cc] = sLog[tok * L_STR + cgl * 10 + cc] + b2[cg * 10 + cc];
      float mx = l[0];
      #pragma unroll
      for (int cc = 1; cc < 10; cc++) mx = fmaxf(mx, l[cc]);
      float sum = 0.0f, num = 0.0f;
      #pragma unroll
      for (int cc = 0; cc < 10; cc++) {
        float e = expf(l[cc] - mx);
        sum += e; num += (float)cc * e;
      }
      float dig = num / sum;
      sDig[tok * 20 + cg] = dig;
      long long gtok = tok0 + tok;
      if (cg < 10) out[OFF_A + gtok * 10 + cg]        = dig;
      else         out[OFF_B + gtok * 10 + (cg - 10)] = dig;
    }
    __syncthreads();
    // re-zero pad rows? not needed: pad region untouched by sLog (L_STR*64*4
    // = 26624 < pad start? pad starts at byte 400 of each 544-byte row; sLog
    // overlaps B2 rows 0..48 — refill pad for those rows before next pass.
    if (p == 0) {
      for (int idx = tid; idx < 128 * 7; idx += 256) {
        int br = idx / 7, bc4 = 25 + idx % 7;
        float4 z; z.x = z.y = z.z = z.w = 0.0f;
        *(float4*)(B2 + br * B_STR + bc4 * 4) = z;
      }
    }
  }

  // ============= modular decode of selected op, per (token, prime) =========
  const int op = g_op[batch];
  if (op >= 0) {
    for (int task = tid; task < TM * 9; task += NTHR) {
      int tok = task / 9, pr = task % 9;
      const float* dg = &sDig[tok * 20];
      float ua = 0.0f, ub = 0.0f;
      #pragma unroll
      for (int k = 0; k < 10; k++) {
        float pw = d_P10F[pr][k];
        ua = fmaf(dg[k],      pw, ua);
        ub = fmaf(dg[10 + k], pw, ub);
      }
      long long pp = d_P[pr];
      float pf = (float)pp;
      long long r;
      if (op == 0) {
        r = llrintf(fmodf(ua + ub, pf)) % pp;
      } else if (op == 1) {
        long long tt = llrintf(fmodf(ua - ub, pf)) % pp;
        r = (tt + pp) % pp;
      } else {
        long long ra = llrintf(fmodf(ua, pf)) % pp;
        long long rb = llrintf(fmodf(ub, pf)) % pp;
        if (op == 2)      r = ra * rb % pp;
        else if (op == 3) r = modpow6(ra, rb, pp);
        else {
          long long inv = modpow6(rb, pp - 2, pp);
          r = (rb == 0) ? 0 : (ra * inv % pp);
        }
      }
      sRes[tok * 9 + pr] = (int)r;
    }
  }
  __syncthreads();

  // ===================== CRT + digits + msb reorder ========================
  if (tid < TM) {
    long long d[10];
    float sign = 0.0f;
    if (op >= 0) {
      long long n = 0;
      #pragma unroll
      for (int pr = 0; pr < 9; pr++)
        n += (long long)sRes[tid * 9 + pr] * d_CRT[pr];
      n %= M_TOT;
      if (op == 1 && n > M_HALF) n -= M_TOT;
      long long a = (n < 0) ? -n : n;
      if (op == 1) sign = (n < 0) ? 1.0f : 0.0f;
      long long tt = a;
      #pragma unroll
      for (int k = 0; k < 10; k++) { d[k] = tt % 10; tt /= 10; }
    } else {
      #pragma unroll
      for (int k = 0; k < 10; k++) d[k] = 0;
    }
    int hi = -1;
    #pragma unroll
    for (int k = 0; k < 10; k++) if (d[k] != 0) hi = k;
    int ns = (hi >= 0) ? hi + 1 : 1;
    #pragma unroll
    for (int i = 0; i < 10; i++)
      sMsb[tid * 12 + i] = (i < ns) ? (float)d[ns - 1 - i] : -1.0f;
    sMsb[tid * 12 + 10] = sign;
  }
  __syncthreads();

  // ====== inject (float4, 192 threads): out = h + gate*eq*(msb@Winj+binj) ==
  if (tid < 192) {
    float4 wv[11];
    #pragma unroll
    for (int k = 0; k < 11; k++)
      wv[k] = *(const float4*)(Winj + k * DD + tid * 4);
    float4 bj = *(const float4*)(binj + tid * 4);
    float gate = (1.0f / (1.0f + expf(-gatep[0]))) * g_eq[batch];

    #pragma unroll 2
    for (int tok = 0; tok < TM; tok++) {
      long long base = (long long)(tok0 + tok) * DD + tid * 4;
      float4 hv = *(const float4*)(h + base);
      float4 inj = bj;
      #pragma unroll
      for (int k = 0; k < 11; k++) {
        float m = sMsb[tok * 12 + k];
        inj.x = fmaf(m, wv[k].x, inj.x);
        inj.y = fmaf(m, wv[k].y, inj.y);
        inj.z = fmaf(m, wv[k].z, inj.z);
        inj.w = fmaf(m, wv[k].w, inj.w);
      }
      float4 o;
      o.x = hv.x + gate * inj.x;
      o.y = hv.y + gate * inj.y;
      o.z = hv.z + gate * inj.z;
      o.w = hv.w + gate * inj.w;
      *(float4*)(out + base) = o;
    }
  }
}

// ---------------------------------------------------------------------------
extern "C" void kernel_launch(void* const* d_in, const int* in_sizes, int n_in,
                              void* d_out, int out_size) {
  (void)in_sizes; (void)n_in; (void)out_size;
  const float* h    = (const float*)d_in[0];
  const float* W1   = (const float*)d_in[1];
  const float* b1   = (const float*)d_in[2];
  const float* W2   = (const float*)d_in[3];
  const float* b2   = (const float*)d_in[4];
  const float* Winj = (const float*)d_in[5];
  const float* binj = (const float*)d_in[6];
  const float* gate = (const float*)d_in[7];
  const int*   ids  = (const int*)d_in[8];
  float* out = (float*)d_out;

  prep_kernel<<<BB, 256>>>(ids);

  cudaFuncSetAttribute(main_kernel, cudaFuncAttributeMaxDynamicSharedMemorySize,
                       SM_TOTAL);
  main_kernel<<<NTOK / TM, NTHR, SM_TOTAL>>>(h, W1, b1, W2, b2, Winj, binj,
                                             gate, out);
}

// round 17
// speedup vs baseline: 1.0470x; 1.0215x over previous
#include <cuda_runtime.h>
#include <math.h>
#include <stdint.h>

#define BB   16
#define SS   2048
#define DD   768
#define MHID 128
#define NCLS 200
#define NTOK (BB*SS)
#define TM   64
#define NTHR 256
#define OFF_A ((long long)NTOK*DD)
#define OFF_B (OFF_A + (long long)NTOK*10)

#define M_TOT  247357937827LL
#define M_HALF 123678968913LL

// ---- SMEM layout ----
// transient union [0, 69632):
//   GEMM1: A0(9216) A1(9216) B0(17408) B1(17408)
//   GEMM2: B2 (128*136*4=69632); sLog (64*104*4) aliases B2
//   inject: Winj staged [16][776] = 49664 B ; msbPad [64][20] = 5120 B
#define SM_A0   0
#define SM_A1   9216
#define SM_B0   18432
#define SM_B1   35840
#define SM_B2   0
#define SM_LOG  0
#define SM_WJ   0
#define SM_MP   49664
// persistent:
#define SM_HID  69632          // 64*132*4 = 33792
#define SM_DIG  103424         // 64*20*4  = 5120
#define SM_RES  108544         // 64*9*4   = 2304
#define SM_TOTAL 110848

#define A_STR 36
#define B_STR 136
#define H_STR 132
#define L_STR 104
#define WJ_STR 776
#define MP_STR 20

static __device__ int   g_op[BB];
static __device__ float g_eq[BB];

__device__ const int d_P[9] = {7,11,13,17,19,23,29,31,37};
__device__ const float d_P10F[9][10] = {
  {1,3,2,6,4,5,1,3,2,6},
  {1,10,1,10,1,10,1,10,1,10},
  {1,10,9,12,3,4,1,10,9,12},
  {1,10,15,14,4,6,9,5,16,7},
  {1,10,5,12,6,3,11,15,17,18},
  {1,10,8,11,18,19,6,14,2,20},
  {1,10,13,14,24,8,22,17,25,18},
  {1,10,7,8,18,25,2,20,14,16},
  {1,10,26,1,10,26,1,10,26,1}};
__device__ const long long d_CRT[9] = {
  35336848261LL, 224870852570LL, 114165202074LL, 218257003965LL,
  78113032998LL, 53773464745LL, 68236672504LL, 223420072876LL,
  220616539143LL};

__device__ __forceinline__ float tf32r(float x) {
  uint32_t u;
  asm("cvt.rna.tf32.f32 %0, %1;" : "=r"(u) : "f"(x));
  return __uint_as_float(u);
}

__device__ __forceinline__ uint32_t smem_u32(const void* p) {
  uint32_t a;
  asm("{ .reg .u64 t; cvta.to.shared.u64 t, %1; cvt.u32.u64 %0, t; }"
      : "=r"(a) : "l"(p));
  return a;
}

__device__ __forceinline__ void ldsm_x4(uint32_t* r, uint32_t a) {
  asm volatile("ldmatrix.sync.aligned.m8n8.x4.shared.b16 {%0,%1,%2,%3}, [%4];"
    : "=r"(r[0]), "=r"(r[1]), "=r"(r[2]), "=r"(r[3]) : "r"(a));
}

__device__ __forceinline__ void mma_tf32(float* c, const uint32_t* a,
                                         const uint32_t* b) {
  asm volatile(
    "mma.sync.aligned.m16n8k8.row.col.f32.tf32.tf32.f32 "
    "{%0,%1,%2,%3}, {%4,%5,%6,%7}, {%8,%9}, {%0,%1,%2,%3};"
    : "+f"(c[0]), "+f"(c[1]), "+f"(c[2]), "+f"(c[3])
    : "r"(a[0]), "r"(a[1]), "r"(a[2]), "r"(a[3]), "r"(b[0]), "r"(b[1]));
}

__device__ __forceinline__ long long modpow6(long long base, long long e, long long p) {
  long long res = 1, b = base % p;
  #pragma unroll
  for (int i = 0; i < 6; i++) {
    if (e & 1) res = res * b % p;
    b = b * b % p;
    e >>= 1;
  }
  return res;
}

// ---------------------------------------------------------------------------
__global__ void prep_kernel(const int* __restrict__ ids) {
  __shared__ int s_min[8], s_eq[8];
  const int b = blockIdx.x;
  const int* row = ids + b * SS;
  int tid = threadIdx.x, lane = tid & 31, w = tid >> 5;
  int minpos = SS, eq = 0;
  for (int i = tid; i < SS; i += 256) {
    int t = row[i];
    eq |= (t == 28);
    if (t >= 20 && t <= 24) minpos = min(minpos, i);
  }
  #pragma unroll
  for (int off = 16; off; off >>= 1) {
    minpos = min(minpos, __shfl_xor_sync(0xffffffffu, minpos, off));
    eq    |= __shfl_xor_sync(0xffffffffu, eq, off);
  }
  if (lane == 0) { s_min[w] = minpos; s_eq[w] = eq; }
  __syncthreads();
  if (tid == 0) {
    int mp = SS, e = 0;
    #pragma unroll
    for (int i = 0; i < 8; i++) { mp = min(mp, s_min[i]); e |= s_eq[i]; }
    int pos = (mp < SS) ? mp : 0;
    int t = row[pos];
    g_op[b] = (t >= 20 && t <= 24) ? (t - 20) : -1;
    g_eq[b] = e ? 1.0f : 0.0f;
  }
}

// ---------------------------------------------------------------------------
__global__ void __launch_bounds__(NTHR, 2)
main_kernel(const float* __restrict__ h,  const float* __restrict__ W1,
            const float* __restrict__ b1, const float* __restrict__ W2,
            const float* __restrict__ b2, const float* __restrict__ Winj,
            const float* __restrict__ binj, const float* __restrict__ gatep,
            float* __restrict__ out) {
  extern __shared__ char sm[];
  const int tid  = threadIdx.x;
  const int wid  = tid >> 5;
  const int lane = tid & 31;
  const int tok0 = blockIdx.x * TM;
  const int batch = tok0 / SS;

  float* sHid = (float*)(sm + SM_HID);
  float* sLog = (float*)(sm + SM_LOG);
  float* sDig = (float*)(sm + SM_DIG);
  int*   sRes = (int*)(sm + SM_RES);
  float* Ws   = (float*)(sm + SM_WJ);
  float* Mp   = (float*)(sm + SM_MP);
  float* Ab[2] = {(float*)(sm + SM_A0), (float*)(sm + SM_A1)};
  float* Bb[2] = {(float*)(sm + SM_B0), (float*)(sm + SM_B1)};
  float* B2 = (float*)(sm + SM_B2);
  const uint32_t sbase = smem_u32(sm);

  // warp tiling: 2x4 warps, each 32 rows x 32 cols
  const int g = lane >> 2, t = lane & 3;
  const int warp_row = (wid & 1) * 32;
  const int warp_col = (wid >> 1) * 32;

  // ldmatrix per-thread addressing (A-side fragments)
  const int lq = lane >> 3;
  const int lrow = (lane & 7) + (lq & 1) * 8;
  const int lcol = (lq >> 1) * 4;
  uint32_t a_off[2], hid_off[2];
  #pragma unroll
  for (int mt = 0; mt < 2; mt++) {
    a_off[mt]   = ((warp_row + mt * 16 + lrow) * A_STR + lcol) * 4;
    hid_off[mt] = SM_HID + ((warp_row + mt * 16 + lrow) * H_STR + lcol) * 4;
  }
  const uint32_t abufoff[2] = {SM_A0, SM_A1};

  // ============ GEMM1 (tf32 mma.sync): hid = relu(h @ W1 + b1) =============
  float acc[2][4][4];
  #pragma unroll
  for (int mt = 0; mt < 2; mt++)
    #pragma unroll
    for (int nt = 0; nt < 4; nt++)
      #pragma unroll
      for (int i = 0; i < 4; i++) acc[mt][nt][i] = 0.0f;

  #pragma unroll
  for (int r = 0; r < 2; r++) {
    int idx = tid + r * 256;
    int ar = idx >> 3, ac4 = idx & 7;
    float4 v = *(const float4*)(h + (long long)(tok0 + ar) * DD + ac4 * 4);
    v.x = tf32r(v.x); v.y = tf32r(v.y); v.z = tf32r(v.z); v.w = tf32r(v.w);
    *(float4*)(Ab[0] + ar * A_STR + ac4 * 4) = v;
  }
  #pragma unroll
  for (int r = 0; r < 4; r++) {
    int idx = tid + r * 256;
    int br = idx >> 5, bc4 = idx & 31;
    float4 w = *(const float4*)(W1 + br * MHID + bc4 * 4);
    w.x = tf32r(w.x); w.y = tf32r(w.y); w.z = tf32r(w.z); w.w = tf32r(w.w);
    *(float4*)(Bb[0] + br * B_STR + bc4 * 4) = w;
  }
  __syncthreads();

  for (int c = 0; c < 24; c++) {
    int cur = c & 1;
    float4 pa[2], pb[4];
    if (c < 23) {
      int k0n = (c + 1) * 32;
      #pragma unroll
      for (int r = 0; r < 2; r++) {
        int idx = tid + r * 256;
        int ar = idx >> 3, ac4 = idx & 7;
        pa[r] = *(const float4*)(h + (long long)(tok0 + ar) * DD + k0n + ac4 * 4);
      }
      #pragma unroll
      for (int r = 0; r < 4; r++) {
        int idx = tid + r * 256;
        int br = idx >> 5, bc4 = idx & 31;
        pb[r] = *(const float4*)(W1 + (k0n + br) * MHID + bc4 * 4);
      }
    }
    const float* B = Bb[cur];
    const uint32_t abase = sbase + abufoff[cur];
    #pragma unroll
    for (int ks = 0; ks < 4; ks++) {
      uint32_t af[2][4];
      ldsm_x4(af[0], abase + a_off[0] + ks * 32);
      ldsm_x4(af[1], abase + a_off[1] + ks * 32);
      uint32_t bf[4][2];
      #pragma unroll
      for (int nt = 0; nt < 4; nt++) {
        const float* bp = B + (ks * 8 + t) * B_STR + warp_col + nt * 8 + g;
        bf[nt][0] = __float_as_uint(bp[0]);
        bf[nt][1] = __float_as_uint(bp[4 * B_STR]);
      }
      #pragma unroll
      for (int mt = 0; mt < 2; mt++)
        #pragma unroll
        for (int nt = 0; nt < 4; nt++)
          mma_tf32(acc[mt][nt], af[mt], bf[nt]);
    }
    // single sync per iteration: STS targets the opposite buffer from all
    // concurrent reads; barrier after STS orders both hazards.
    if (c < 23) {
      int nxt = (c + 1) & 1;
      #pragma unroll
      for (int r = 0; r < 2; r++) {
        int idx = tid + r * 256;
        int ar = idx >> 3, ac4 = idx & 7;
        float4 v = pa[r];
        v.x = tf32r(v.x); v.y = tf32r(v.y); v.z = tf32r(v.z); v.w = tf32r(v.w);
        *(float4*)(Ab[nxt] + ar * A_STR + ac4 * 4) = v;
      }
      #pragma unroll
      for (int r = 0; r < 4; r++) {
        int idx = tid + r * 256;
        int br = idx >> 5, bc4 = idx & 31;
        float4 w = pb[r];
        w.x = tf32r(w.x); w.y = tf32r(w.y); w.z = tf32r(w.z); w.w = tf32r(w.w);
        *(float4*)(Bb[nxt] + br * B_STR + bc4 * 4) = w;
      }
    }
    __syncthreads();
  }

  // ---- GEMM1 epilogue: bias + relu + tf32 -> sHid ----
  #pragma unroll
  for (int mt = 0; mt < 2; mt++) {
    int row0 = warp_row + mt * 16 + g;
    #pragma unroll
    for (int nt = 0; nt < 4; nt++) {
      int col = warp_col + nt * 8 + 2 * t;
      float bx = b1[col], by = b1[col + 1];
      sHid[row0 * H_STR + col]       = tf32r(fmaxf(acc[mt][nt][0] + bx, 0.0f));
      sHid[row0 * H_STR + col + 1]   = tf32r(fmaxf(acc[mt][nt][1] + by, 0.0f));
      sHid[(row0+8) * H_STR + col]   = tf32r(fmaxf(acc[mt][nt][2] + bx, 0.0f));
      sHid[(row0+8) * H_STR + col+1] = tf32r(fmaxf(acc[mt][nt][3] + by, 0.0f));
    }
  }
  __syncthreads();

  // ============ GEMM2 (tf32 mma.sync) in 2 passes of 100 cols ==============
  for (int idx = tid; idx < 128 * 7; idx += 256) {   // zero pad cols 100..127
    int br = idx / 7, bc4 = 25 + idx % 7;
    float4 z; z.x = z.y = z.z = z.w = 0.0f;
    *(float4*)(B2 + br * B_STR + bc4 * 4) = z;
  }
  for (int p = 0; p < 2; p++) {
    #pragma unroll
    for (int r = 0; r < 13; r++) {
      int idx = tid + r * 256;
      if (idx < 3200) {
        int br = idx / 25, bc4 = idx % 25;
        float4 w = *(const float4*)(W2 + br * NCLS + p * 100 + bc4 * 4);
        w.x = tf32r(w.x); w.y = tf32r(w.y); w.z = tf32r(w.z); w.w = tf32r(w.w);
        *(float4*)(B2 + br * B_STR + bc4 * 4) = w;
      }
    }
    __syncthreads();

    #pragma unroll
    for (int mt = 0; mt < 2; mt++)
      #pragma unroll
      for (int nt = 0; nt < 4; nt++)
        #pragma unroll
        for (int i = 0; i < 4; i++) acc[mt][nt][i] = 0.0f;

    #pragma unroll 4
    for (int ks = 0; ks < 16; ks++) {
      uint32_t af[2][4];
      ldsm_x4(af[0], sbase + hid_off[0] + ks * 32);
      ldsm_x4(af[1], sbase + hid_off[1] + ks * 32);
      uint32_t bf[4][2];
      #pragma unroll
      for (int nt = 0; nt < 4; nt++) {
        const float* bp = B2 + (ks * 8 + t) * B_STR + warp_col + nt * 8 + g;
        bf[nt][0] = __float_as_uint(bp[0]);
        bf[nt][1] = __float_as_uint(bp[4 * B_STR]);
      }
      #pragma unroll
      for (int mt = 0; mt < 2; mt++)
        #pragma unroll
        for (int nt = 0; nt < 4; nt++)
          mma_tf32(acc[mt][nt], af[mt], bf[nt]);
    }
    __syncthreads();   // all warps done reading B2 before sLog overwrites it

    #pragma unroll
    for (int mt = 0; mt < 2; mt++) {
      int row0 = warp_row + mt * 16 + g;
      #pragma unroll
      for (int nt = 0; nt < 4; nt++) {
        int col = warp_col + nt * 8 + 2 * t;
        if (col < 100) {
          sLog[row0 * L_STR + col]       = acc[mt][nt][0];
          sLog[row0 * L_STR + col + 1]   = acc[mt][nt][1];
          sLog[(row0+8) * L_STR + col]   = acc[mt][nt][2];
          sLog[(row0+8) * L_STR + col+1] = acc[mt][nt][3];
        }
      }
    }
    __syncthreads();

    for (int ti = tid; ti < TM * 10; ti += NTHR) {
      int tok = ti / 10, cgl = ti % 10;
      int cg = p * 10 + cgl;
      float l[10];
      #pragma unroll
      for (int cc = 0; cc < 10; cc++)
        l[cc] = sLog[tok * L_STR + cgl * 10 + cc] + b2[cg * 10 + cc];
      float mx = l[0];
      #pragma unroll
      for (int cc = 1; cc < 10; cc++) mx = fmaxf(mx, l[cc]);
      float sum = 0.0f, num = 0.0f;
      #pragma unroll
      for (int cc = 0; cc < 10; cc++) {
        float e = expf(l[cc] - mx);
        sum += e; num += (float)cc * e;
      }
      float dig = num / sum;
      sDig[tok * 20 + cg] = dig;
      long long gtok = tok0 + tok;
      if (cg < 10) out[OFF_A + gtok * 10 + cg]        = dig;
      else         out[OFF_B + gtok * 10 + (cg - 10)] = dig;
    }
    __syncthreads();
    if (p == 0) {    // refill pad region clobbered by sLog
      for (int idx = tid; idx < 128 * 7; idx += 256) {
        int br = idx / 7, bc4 = 25 + idx % 7;
        float4 z; z.x = z.y = z.z = z.w = 0.0f;
        *(float4*)(B2 + br * B_STR + bc4 * 4) = z;
      }
    }
  }

  // ---- stage Winj (tf32-rounded, K padded to 16) into freed transient SMEM
  for (int i4 = tid; i4 < 16 * 194; i4 += 256) {
    int k = i4 / 194, c4 = i4 % 194;
    float4 w; w.x = w.y = w.z = w.w = 0.0f;
    if (k < 11 && c4 < 192) {
      w = *(const float4*)(Winj + k * DD + c4 * 4);
      w.x = tf32r(w.x); w.y = tf32r(w.y); w.z = tf32r(w.z); w.w = tf32r(w.w);
    }
    *(float4*)(Ws + k * WJ_STR + c4 * 4) = w;
  }

  // ============= modular decode of selected op, per (token, prime) =========
  const int op = g_op[batch];
  if (op >= 0) {
    for (int task = tid; task < TM * 9; task += NTHR) {
      int tok = task / 9, pr = task % 9;
      const float* dg = &sDig[tok * 20];
      float ua = 0.0f, ub = 0.0f;
      #pragma unroll
      for (int k = 0; k < 10; k++) {
        float pw = d_P10F[pr][k];
        ua = fmaf(dg[k],      pw, ua);
        ub = fmaf(dg[10 + k], pw, ub);
      }
      long long pp = d_P[pr];
      float pf = (float)pp;
      long long r;
      if (op == 0) {
        r = llrintf(fmodf(ua + ub, pf)) % pp;
      } else if (op == 1) {
        long long tt = llrintf(fmodf(ua - ub, pf)) % pp;
        r = (tt + pp) % pp;
      } else {
        long long ra = llrintf(fmodf(ua, pf)) % pp;
        long long rb = llrintf(fmodf(ub, pf)) % pp;
        if (op == 2)      r = ra * rb % pp;
        else if (op == 3) r = modpow6(ra, rb, pp);
        else {
          long long inv = modpow6(rb, pp - 2, pp);
          r = (rb == 0) ? 0 : (ra * inv % pp);
        }
      }
      sRes[tok * 9 + pr] = (int)r;
    }
  }
  __syncthreads();

  // ===================== CRT + digits + msb reorder -> Mp ==================
  if (tid < TM) {
    long long d[10];
    float sign = 0.0f;
    if (op >= 0) {
      long long n = 0;
      #pragma unroll
      for (int pr = 0; pr < 9; pr++)
        n += (long long)sRes[tid * 9 + pr] * d_CRT[pr];
      n %= M_TOT;
      if (op == 1 && n > M_HALF) n -= M_TOT;
      long long a = (n < 0) ? -n : n;
      if (op == 1) sign = (n < 0) ? 1.0f : 0.0f;
      long long tt = a;
      #pragma unroll
      for (int k = 0; k < 10; k++) { d[k] = tt % 10; tt /= 10; }
    } else {
      #pragma unroll
      for (int k = 0; k < 10; k++) d[k] = 0;
    }
    int hi = -1;
    #pragma unroll
    for (int k = 0; k < 10; k++) if (d[k] != 0) hi = k;
    int ns = (hi >= 0) ? hi + 1 : 1;
    float* mp = Mp + tid * MP_STR;
    #pragma unroll
    for (int i = 0; i < 10; i++)
      mp[i] = (i < ns) ? (float)d[ns - 1 - i] : -1.0f;
    mp[10] = sign;
    #pragma unroll
    for (int i = 11; i < 16; i++) mp[i] = 0.0f;
  }
  __syncthreads();

  // ========== inject via tf32 mma: out = h + gate*eq*(msb@Winj + binj) =====
  {
    float gate = (1.0f / (1.0f + expf(-gatep[0]))) * g_eq[batch];
    const int n0w = wid * 96;
    #pragma unroll 1
    for (int mtile = 0; mtile < 4; mtile++) {
      int row0 = mtile * 16;
      uint32_t af0[4], af1[4];
      {
        const float* mp0 = Mp + (row0 + g) * MP_STR + t;
        af0[0] = __float_as_uint(mp0[0]);
        af0[1] = __float_as_uint(mp0[8 * MP_STR]);
        af0[2] = __float_as_uint(mp0[4]);
        af0[3] = __float_as_uint(mp0[8 * MP_STR + 4]);
        const float* mp1 = mp0 + 8;
        af1[0] = __float_as_uint(mp1[0]);
        af1[1] = __float_as_uint(mp1[8 * MP_STR]);
        af1[2] = __float_as_uint(mp1[4]);
        af1[3] = __float_as_uint(mp1[8 * MP_STR + 4]);
      }
      float acc2[12][4];
      #pragma unroll
      for (int nt = 0; nt < 12; nt++)
        #pragma unroll
        for (int i = 0; i < 4; i++) acc2[nt][i] = 0.0f;

      #pragma unroll
      for (int nt = 0; nt < 12; nt++) {
        const float* bp = Ws + t * WJ_STR + n0w + nt * 8 + g;
        uint32_t bf0[2] = {__float_as_uint(bp[0]),
                           __float_as_uint(bp[4 * WJ_STR])};
        mma_tf32(acc2[nt], af0, bf0);
        const float* bp1 = bp + 8 * WJ_STR;
        uint32_t bf1[2] = {__float_as_uint(bp1[0]),
                           __float_as_uint(bp1[4 * WJ_STR])};
        mma_tf32(acc2[nt], af1, bf1);
      }
      #pragma unroll
      for (int nt = 0; nt < 12; nt++) {
        int col = n0w + nt * 8 + 2 * t;
        float2 bj = *(const float2*)(binj + col);
        long long b0 = (long long)(tok0 + row0 + g) * DD + col;
        float2 h0 = *(const float2*)(h + b0);
        float2 o0;
        o0.x = h0.x + gate * (acc2[nt][0] + bj.x);
        o0.y = h0.y + gate * (acc2[nt][1] + bj.y);
        *(float2*)(out + b0) = o0;
        long long b1 = b0 + 8LL * DD;
        float2 h1 = *(const float2*)(h + b1);
        float2 o1;
        o1.x = h1.x + gate * (acc2[nt][2] + bj.x);
        o1.y = h1.y + gate * (acc2[nt][3] + bj.y);
        *(float2*)(out + b1) = o1;
      }
    }
  }
}

// ---------------------------------------------------------------------------
extern "C" void kernel_launch(void* const* d_in, const int* in_sizes, int n_in,
                              void* d_out, int out_size) {
  (void)in_sizes; (void)n_in; (void)out_size;
  const float* h    = (const float*)d_in[0];
  const float* W1   = (const float*)d_in[1];
  const float* b1   = (const float*)d_in[2];
  const float* W2   = (const float*)d_in[3];
  const float* b2   = (const float*)d_in[4];
  const float* Winj = (const float*)d_in[5];
  const float* binj = (const float*)d_in[6];
  const float* gate = (const float*)d_in[7];
  const int*   ids  = (const int*)d_in[8];
  float* out = (float*)d_out;

  prep_kernel<<<BB, 256>>>(ids);

  cudaFuncSetAttribute(main_kernel, cudaFuncAttributeMaxDynamicSharedMemorySize,
                       SM_TOTAL);
  main_kernel<<<NTOK / TM, NTHR, SM_TOTAL>>>(h, W1, b1, W2, b2, Winj, binj,
                                             gate, out);
}